// round 9
// baseline (speedup 1.0000x reference)
#include <cuda_runtime.h>
#include <cuda_fp16.h>
#include <cstdint>

// PatchMerging fused as fp16 mma.sync GEMM (fp32 accumulate):
//   out[m,o] = rstd_m * dot(y_m, Wg[o,:]) + (bias_o - rstd_m*mu_m*s_o)
// R9: N split across CTA pairs (N=96 each) -> 24-reg accumulators -> 3 CTAs/SM.
//     Twin CTAs adjacent in launch order so A reads share L2.

#define M_TOTAL 65536
#define KDIM    768
#define NDIM    192
#define CH      96
#define BM      64
#define TB      256
#define NCHUNK  8        // K chunks of 96 floats (one patch segment each)
#define APITCH  52       // A row pitch in uint32 (48 data + 4 pad)
#define NT_CTA  12       // 12 n-tiles of 8 -> N=96 per CTA

// ---- device scratch ----
// B fragment-major fp16, per chunk 9216 uint32 (nt-major: nt 0..11 | 12..23):
//   idx = chunk*9216 + ((nt*6 + ks)*64 + lane*2 + reg)
__device__ uint32_t g_WgH[NCHUNK * 9216];
__device__ float g_s[NDIM];
__device__ float g_bias[NDIM];

#define MMA_FP16(d, a, b0, b1)                                               \
    asm volatile("mma.sync.aligned.m16n8k16.row.col.f32.f16.f16.f32 "        \
                 "{%0,%1,%2,%3}, {%4,%5,%6,%7}, {%8,%9}, {%0,%1,%2,%3};"     \
                 : "+f"((d)[0]), "+f"((d)[1]), "+f"((d)[2]), "+f"((d)[3])    \
                 : "r"((a)[0]), "r"((a)[1]), "r"((a)[2]), "r"((a)[3]),       \
                   "r"(b0), "r"(b1))

__device__ __forceinline__ void cp_async16(uint32_t dst, const void* src) {
    asm volatile("cp.async.cg.shared.global [%0], [%1], 16;" :: "r"(dst), "l"(src));
}
__device__ __forceinline__ uint32_t pack_h2(float a, float b) {
    __half2 h = __floats2half2_rn(a, b);
    return *(uint32_t*)&h;
}

// ---- prep: frag blocks + warp-per-output fold blocks ----
#define NFRAG (NCHUNK * 9216)
#define FRAG_BLOCKS (NFRAG / 256)          // 288
#define COL_BLOCKS  (NDIM / 8)             // 24
__global__ void pm_prep(const float* __restrict__ ln_w, const float* __restrict__ ln_b,
                        const float* __restrict__ W) {
    int bid = blockIdx.x;
    if (bid < FRAG_BLOCKS) {
        int idx = bid * 256 + threadIdx.x;
        int chunk = idx / 9216, rem = idx % 9216;
        int nt = rem / 384, r2 = rem % 384;
        int ks = r2 >> 6, w = r2 & 63;
        int lane = w >> 1, reg = w & 1;
        int k0 = chunk * 96 + ks * 16 + reg * 8 + (lane & 3) * 2;
        int n = nt * 8 + (lane >> 2);
        g_WgH[idx] = pack_h2(ln_w[k0] * W[n * KDIM + k0],
                             ln_w[k0 + 1] * W[n * KDIM + k0 + 1]);
    } else {
        int wlocal = threadIdx.x >> 5, lane = threadIdx.x & 31;
        int o = (bid - FRAG_BLOCKS) * 8 + wlocal;
        const float* wr = W + o * KDIM;
        float s = 0.f, b = 0.f;
#pragma unroll
        for (int i = 0; i < KDIM / 32; ++i) {
            int c = lane + i * 32;
            float w = wr[c];
            s = fmaf(ln_w[c], w, s);
            b = fmaf(ln_b[c], w, b);
        }
#pragma unroll
        for (int d = 16; d > 0; d >>= 1) {
            s += __shfl_xor_sync(0xffffffffu, s, d);
            b += __shfl_xor_sync(0xffffffffu, b, d);
        }
        if (lane == 0) {
            g_s[o] = s;
            g_bias[o] = b;
        }
    }
}

// ---- smem uint32-index layout ----
#define SA0      0          // 64*52 = 3328 words per buffer
#define SA1      3328
#define SB0      6656       // 4608 words per buffer (12 nt x 6 ks x 64)
#define SB1      11264
#define SM_PSUM  15872      // 256
#define SM_PSQ   16128      // 256
#define SM_RSTD  16384      // 64
#define SM_RMU   16448      // 64
#define SM_SFOLD 16512      // 192
#define SM_BFOLD 16704      // 192
#define SM_WORDS 16896      // 67584 bytes -> 3 CTAs/SM = 203KB

__global__ __launch_bounds__(TB, 3) void pm_main(const float* __restrict__ x,
                                                 float* __restrict__ out) {
    extern __shared__ uint32_t sm[];
    uint32_t* As[2] = {sm + SA0, sm + SA1};
    uint32_t* Bs[2] = {sm + SB0, sm + SB1};
    float* smf = (float*)sm;

    const int tid = threadIdx.x, lane = tid & 31, wid = tid >> 5;
    const int mw = wid >> 2, nw = wid & 3;       // 2x4 warp grid: warptile 32(M) x 24(N)
    const int nhalf = blockIdx.x;                // fastest-varying: twins adjacent for L2
    const int bm = blockIdx.y;

    // A-gather: 4 threads per row; per half-chunk each thread moves 12 floats
    const int r = tid >> 2, h = tid & 3;
    const int m = bm * BM + r;
    const int ww = m & 31, hh = (m >> 5) & 31, dd = (m >> 10) & 31, bb = m >> 15;
    const float* xbase = x + ((((long)bb * 64 + 2 * dd) * 64 + 2 * hh) * 64 + 2 * ww) * CH;

    float acc[2][3][4];
#pragma unroll
    for (int i = 0; i < 2; ++i)
#pragma unroll
        for (int j = 0; j < 3; ++j)
#pragma unroll
            for (int u = 0; u < 4; ++u) acc[i][j][u] = 0.f;

    float psum = 0.f, psq = 0.f;
    float4 av[3];

    auto ldg_half = [&](int ch, int half) {
        const float* p = xbase + ((ch >> 2) & 1) * 393216 + ((ch >> 1) & 1) * 6144 +
                         (ch & 1) * 96 + half * 48 + h * 12;
        av[0] = *(const float4*)(p);
        av[1] = *(const float4*)(p + 4);
        av[2] = *(const float4*)(p + 8);
    };
    auto sts_half = [&](uint32_t* Ad, int half) {
        uint32_t* dst = Ad + r * APITCH + half * 24 + h * 6;
#pragma unroll
        for (int v = 0; v < 3; ++v) {
            float4 t4 = av[v];
            psum += t4.x + t4.y + t4.z + t4.w;
            psq = fmaf(t4.x, t4.x, psq);
            psq = fmaf(t4.y, t4.y, psq);
            psq = fmaf(t4.z, t4.z, psq);
            psq = fmaf(t4.w, t4.w, psq);
            uint2 pk;
            pk.x = pack_h2(t4.x, t4.y);
            pk.y = pack_h2(t4.z, t4.w);
            *(uint2*)(dst + v * 2) = pk;
        }
    };
    auto cpB = [&](int ch, uint32_t* Bd) {
        const uint4* src = (const uint4*)(g_WgH + ch * 9216 + nhalf * 4608);
        uint32_t dst = (uint32_t)__cvta_generic_to_shared(Bd);
#pragma unroll
        for (int i = 0; i < 4; ++i)
            cp_async16(dst + (tid + i * TB) * 16, src + tid + i * TB);
        if (tid < 128) cp_async16(dst + (tid + 4 * TB) * 16, src + tid + 4 * TB);
    };
    auto compute_half = [&](const uint32_t* Ad, const uint32_t* Bd, int ks0) {
#pragma unroll
        for (int kk = 0; kk < 3; ++kk) {
            const int ks = ks0 + kk;
            uint32_t a[2][4];
#pragma unroll
            for (int tmi = 0; tmi < 2; ++tmi) {
                int row = mw * 32 + tmi * 16 + (lane & 15);
                const uint32_t* ap = Ad + row * APITCH + ks * 8 + (lane >> 4) * 4;
                uint32_t sa = (uint32_t)__cvta_generic_to_shared(ap);
                asm volatile("ldmatrix.sync.aligned.m8n8.x4.shared.b16 {%0,%1,%2,%3}, [%4];"
                             : "=r"(a[tmi][0]), "=r"(a[tmi][1]), "=r"(a[tmi][2]), "=r"(a[tmi][3])
                             : "r"(sa));
            }
#pragma unroll
            for (int nt = 0; nt < 3; ++nt) {
                uint2 b = *(const uint2*)(Bd + (((nw * 3 + nt) * 6 + ks) * 64 + lane * 2));
                MMA_FP16(acc[0][nt], a[0], b.x, b.y);
                MMA_FP16(acc[1][nt], a[1], b.x, b.y);
            }
        }
    };

    // prologue: chunk 0
    cpB(0, Bs[0]);
    ldg_half(0, 0); sts_half(As[0], 0);
    ldg_half(0, 1); sts_half(As[0], 1);
    asm volatile("cp.async.commit_group;" ::: "memory");
    asm volatile("cp.async.wait_group 0;" ::: "memory");
    __syncthreads();

    int cur = 0;
    for (int c = 0; c < NCHUNK; ++c) {
        const bool more = (c + 1 < NCHUNK);
        if (more) {
            cpB(c + 1, Bs[cur ^ 1]);
            asm volatile("cp.async.commit_group;" ::: "memory");
            ldg_half(c + 1, 0);
        }
        compute_half(As[cur], Bs[cur], 0);
        if (more) {
            sts_half(As[cur ^ 1], 0);
            ldg_half(c + 1, 1);
        }
        compute_half(As[cur], Bs[cur], 3);
        if (more) {
            sts_half(As[cur ^ 1], 1);
            asm volatile("cp.async.wait_group 0;" ::: "memory");
        }
        __syncthreads();
        cur ^= 1;
    }

    // ---- LN stats reduce + fold constants ----
    smf[SM_PSUM + tid] = psum;
    smf[SM_PSQ + tid] = psq;
    if (tid < NDIM) {
        smf[SM_SFOLD + tid] = g_s[tid];
        smf[SM_BFOLD + tid] = g_bias[tid];
    }
    __syncthreads();
    if (tid < BM) {
        float su = smf[SM_PSUM + 4 * tid] + smf[SM_PSUM + 4 * tid + 1] +
                   smf[SM_PSUM + 4 * tid + 2] + smf[SM_PSUM + 4 * tid + 3];
        float sq = smf[SM_PSQ + 4 * tid] + smf[SM_PSQ + 4 * tid + 1] +
                   smf[SM_PSQ + 4 * tid + 2] + smf[SM_PSQ + 4 * tid + 3];
        float mu = su * (1.f / 768.f);
        float var = sq * (1.f / 768.f) - mu * mu;
        float rs = rsqrtf(var + 1e-5f);
        smf[SM_RSTD + tid] = rs;
        smf[SM_RMU + tid] = rs * mu;
    }
    __syncthreads();

    // ---- epilogue: LN fold + store ----
#pragma unroll
    for (int tmi = 0; tmi < 2; ++tmi) {
        const int rbase = mw * 32 + tmi * 16 + (lane >> 2);
#pragma unroll
        for (int half = 0; half < 2; ++half) {
            const int rr = rbase + half * 8;
            const float rs = smf[SM_RSTD + rr];
            const float rm = smf[SM_RMU + rr];
            float* op = out + (size_t)(bm * BM + rr) * NDIM;
#pragma unroll
            for (int nt = 0; nt < 3; ++nt) {
                const int n0 = nhalf * 96 + nw * 24 + nt * 8 + (lane & 3) * 2;
                float2 v;
                v.x = fmaf(rs, acc[tmi][nt][half * 2 + 0], smf[SM_BFOLD + n0] - rm * smf[SM_SFOLD + n0]);
                v.y = fmaf(rs, acc[tmi][nt][half * 2 + 1], smf[SM_BFOLD + n0 + 1] - rm * smf[SM_SFOLD + n0 + 1]);
                *(float2*)(op + n0) = v;
            }
        }
    }
}

extern "C" void kernel_launch(void* const* d_in, const int* in_sizes, int n_in,
                              void* d_out, int out_size) {
    const float* x    = (const float*)d_in[0];   // [2,64,64,64,96]
    const float* ln_w = (const float*)d_in[1];   // [768]
    const float* ln_b = (const float*)d_in[2];   // [768]
    const float* W    = (const float*)d_in[3];   // [192,768]
    float* out = (float*)d_out;                  // [65536,192]
    (void)in_sizes; (void)n_in; (void)out_size;

    cudaFuncSetAttribute(pm_main, cudaFuncAttributeMaxDynamicSharedMemorySize,
                         SM_WORDS * 4);

    pm_prep<<<FRAG_BLOCKS + COL_BLOCKS, 256>>>(ln_w, ln_b, W);
    dim3 grid(2, M_TOTAL / BM);                  // nhalf fastest -> twins share L2
    pm_main<<<grid, TB, SM_WORDS * 4>>>(x, out);
}

// round 13
// speedup vs baseline: 1.2258x; 1.2258x over previous
#include <cuda_runtime.h>
#include <cuda_fp16.h>
#include <cstdint>

// PatchMerging fused as fp16 mma.sync GEMM (fp32 accumulate):
//   out[m,o] = rstd_m * dot(y_m, Wg[o,:]) + (bias_o - rstd_m*mu_m*s_o)
// R10: R8 shape (BM=64, N=192, 2 CTAs/SM) + cp.async.bulk for B (1 instr / 36KB chunk,
//      mbarrier completion) + STS.128 A staging. Attacks the measured LSU bottleneck.

#define M_TOTAL 65536
#define KDIM    768
#define NDIM    192
#define CH      96
#define BM      64
#define TB      256
#define NCHUNK  8        // K chunks of 96 floats (one patch segment each)
#define APITCH  52       // A row pitch in uint32 (48 data + 4 pad; ldmatrix conflict-free)
#define BWORDS  9216     // B words per chunk
#define BBYTES  (BWORDS * 4)

// ---- device scratch ----
// B fragment-major fp16, per chunk 9216 uint32:
//   idx = chunk*9216 + ((nt*6 + ks)*64 + lane*2 + reg), nt 0..23, ks 0..5
__device__ uint32_t g_WgH[NCHUNK * BWORDS];
__device__ float g_s[NDIM];
__device__ float g_bias[NDIM];

#define MMA_FP16(d, a, b0, b1)                                               \
    asm volatile("mma.sync.aligned.m16n8k16.row.col.f32.f16.f16.f32 "        \
                 "{%0,%1,%2,%3}, {%4,%5,%6,%7}, {%8,%9}, {%0,%1,%2,%3};"     \
                 : "+f"((d)[0]), "+f"((d)[1]), "+f"((d)[2]), "+f"((d)[3])    \
                 : "r"((a)[0]), "r"((a)[1]), "r"((a)[2]), "r"((a)[3]),       \
                   "r"(b0), "r"(b1))

__device__ __forceinline__ uint32_t pack_h2(float a, float b) {
    __half2 h = __floats2half2_rn(a, b);
    return *(uint32_t*)&h;
}

#define MBAR_INIT(a, n) \
    asm volatile("mbarrier.init.shared.b64 [%0], %1;" :: "r"((uint32_t)(a)), "r"((uint32_t)(n)) : "memory")
#define MBAR_EXPECT_TX(a, bytes) \
    asm volatile("mbarrier.arrive.expect_tx.shared.b64 _, [%0], %1;" \
                 :: "r"((uint32_t)(a)), "r"((uint32_t)(bytes)) : "memory")
#define BULK_G2S(dst, src, bytes, mbar) \
    asm volatile("cp.async.bulk.shared::cluster.global.mbarrier::complete_tx::bytes " \
                 "[%0], [%1], %2, [%3];" \
                 :: "r"((uint32_t)(dst)), "l"(src), "r"((uint32_t)(bytes)), \
                    "r"((uint32_t)(mbar)) : "memory")
#define MBAR_WAIT(mb, par) do { \
    uint32_t _mb = (uint32_t)(mb), _pa = (uint32_t)(par), _done; \
    asm volatile("{\n\t.reg .pred p;\n\tmbarrier.try_wait.parity.acquire.cta.shared::cta.b64 p, [%1], %2;\n\tselp.b32 %0,1,0,p;\n\t}" \
        : "=r"(_done) : "r"(_mb), "r"(_pa) : "memory"); \
    if (!_done) { \
        asm volatile("{\n\t.reg .pred P1;\n\tWL%=:\n\tmbarrier.try_wait.parity.acquire.cta.shared::cta.b64 P1, [%0], %1, 0x989680;\n\t@P1 bra.uni WD%=;\n\tbra.uni WL%=;\n\tWD%=:\n\t}" \
            :: "r"(_mb), "r"(_pa) : "memory"); \
    } \
} while (0)

// ---- prep: frag blocks + warp-per-output fold blocks ----
#define NFRAG (NCHUNK * BWORDS)
#define FRAG_BLOCKS (NFRAG / 256)          // 288
#define COL_BLOCKS  (NDIM / 8)             // 24
__global__ void pm_prep(const float* __restrict__ ln_w, const float* __restrict__ ln_b,
                        const float* __restrict__ W) {
    int bid = blockIdx.x;
    if (bid < FRAG_BLOCKS) {
        int idx = bid * 256 + threadIdx.x;
        int chunk = idx / BWORDS, rem = idx % BWORDS;
        int nt = rem / 384, r2 = rem % 384;
        int ks = r2 >> 6, w = r2 & 63;
        int lane = w >> 1, reg = w & 1;
        int k0 = chunk * 96 + ks * 16 + reg * 8 + (lane & 3) * 2;
        int n = nt * 8 + (lane >> 2);
        g_WgH[idx] = pack_h2(ln_w[k0] * W[n * KDIM + k0],
                             ln_w[k0 + 1] * W[n * KDIM + k0 + 1]);
    } else {
        int wlocal = threadIdx.x >> 5, lane = threadIdx.x & 31;
        int o = (bid - FRAG_BLOCKS) * 8 + wlocal;
        const float* wr = W + o * KDIM;
        float s = 0.f, b = 0.f;
#pragma unroll
        for (int i = 0; i < KDIM / 32; ++i) {
            int c = lane + i * 32;
            float w = wr[c];
            s = fmaf(ln_w[c], w, s);
            b = fmaf(ln_b[c], w, b);
        }
#pragma unroll
        for (int d = 16; d > 0; d >>= 1) {
            s += __shfl_xor_sync(0xffffffffu, s, d);
            b += __shfl_xor_sync(0xffffffffu, b, d);
        }
        if (lane == 0) {
            g_s[o] = s;
            g_bias[o] = b;
        }
    }
}

// ---- smem uint32-index layout ----
#define SA0      0          // 64*52 = 3328 words per buffer
#define SA1      3328
#define SB0      6656       // 9216 words per buffer
#define SB1      15872
#define SM_MBAR  25088      // 2 x b64 (word idx even -> 8B aligned)
#define SM_PSUM  25092      // 256
#define SM_PSQ   25348      // 256
#define SM_RSTD  25604      // 64
#define SM_RMU   25668      // 64
#define SM_SFOLD 25732      // 192
#define SM_BFOLD 25924      // 192
#define SM_WORDS 26116      // 104464 bytes -> 2 CTAs/SM

__global__ __launch_bounds__(TB, 2) void pm_main(const float* __restrict__ x,
                                                 float* __restrict__ out) {
    extern __shared__ uint32_t sm[];
    uint32_t* As[2] = {sm + SA0, sm + SA1};
    uint32_t* Bs[2] = {sm + SB0, sm + SB1};
    float* smf = (float*)sm;
    const uint32_t sb_mbar = (uint32_t)__cvta_generic_to_shared(sm + SM_MBAR);
    const uint32_t sb_b[2] = {(uint32_t)__cvta_generic_to_shared(sm + SB0),
                              (uint32_t)__cvta_generic_to_shared(sm + SB1)};

    const int tid = threadIdx.x, lane = tid & 31, wid = tid >> 5;
    const int mw = wid >> 2, nw = wid & 3;       // 2x4 warp grid: warptile 32(M) x 48(N)
    const int bm = blockIdx.x;

    // A-gather: 4 threads per row, thread owns 24 contiguous floats of the 96-chunk
    const int r = tid >> 2, h = tid & 3;
    const int m = bm * BM + r;
    const int ww = m & 31, hh = (m >> 5) & 31, dd = (m >> 10) & 31, bb = m >> 15;
    const float* xbase = x + ((((long)bb * 64 + 2 * dd) * 64 + 2 * hh) * 64 + 2 * ww) * CH + h * 24;

    if (tid == 0) {
        MBAR_INIT(sb_mbar, 1);
        MBAR_INIT(sb_mbar + 8, 1);
    }

    float acc[2][6][4];
#pragma unroll
    for (int i = 0; i < 2; ++i)
#pragma unroll
        for (int j = 0; j < 6; ++j)
#pragma unroll
            for (int u = 0; u < 4; ++u) acc[i][j][u] = 0.f;

    float psum = 0.f, psq = 0.f;
    float4 av[2];

    auto segp = [&](int ch) {
        return xbase + ((ch >> 2) & 1) * 393216 + ((ch >> 1) & 1) * 6144 + (ch & 1) * 96;
    };
    // step s covers floats [h*24 + s*8, +8)
    auto ldg_step = [&](int ch, int s) {
        const float* p = segp(ch) + s * 8;
        av[0] = *(const float4*)(p);
        av[1] = *(const float4*)(p + 4);
    };
    auto sts_step = [&](uint32_t* Ad, int s) {
        uint4 pk;
        float4 t4 = av[0];
        psum += t4.x + t4.y + t4.z + t4.w;
        psq = fmaf(t4.x, t4.x, psq); psq = fmaf(t4.y, t4.y, psq);
        psq = fmaf(t4.z, t4.z, psq); psq = fmaf(t4.w, t4.w, psq);
        pk.x = pack_h2(t4.x, t4.y);
        pk.y = pack_h2(t4.z, t4.w);
        t4 = av[1];
        psum += t4.x + t4.y + t4.z + t4.w;
        psq = fmaf(t4.x, t4.x, psq); psq = fmaf(t4.y, t4.y, psq);
        psq = fmaf(t4.z, t4.z, psq); psq = fmaf(t4.w, t4.w, psq);
        pk.z = pack_h2(t4.x, t4.y);
        pk.w = pack_h2(t4.z, t4.w);
        *(uint4*)(Ad + r * APITCH + h * 12 + s * 4) = pk;   // STS.128, 16B aligned
    };
    auto compute_pair = [&](const uint32_t* Ad, const uint32_t* Bd, int ks0) {
#pragma unroll
        for (int kk = 0; kk < 2; ++kk) {
            const int ks = ks0 + kk;
            uint32_t a[2][4];
#pragma unroll
            for (int tmi = 0; tmi < 2; ++tmi) {
                int row = mw * 32 + tmi * 16 + (lane & 15);
                const uint32_t* ap = Ad + row * APITCH + ks * 8 + (lane >> 4) * 4;
                uint32_t sa = (uint32_t)__cvta_generic_to_shared(ap);
                asm volatile("ldmatrix.sync.aligned.m8n8.x4.shared.b16 {%0,%1,%2,%3}, [%4];"
                             : "=r"(a[tmi][0]), "=r"(a[tmi][1]), "=r"(a[tmi][2]), "=r"(a[tmi][3])
                             : "r"(sa));
            }
#pragma unroll
            for (int nt = 0; nt < 6; ++nt) {
                uint2 b = *(const uint2*)(Bd + (((nw * 6 + nt) * 6 + ks) * 64 + lane * 2));
                MMA_FP16(acc[0][nt], a[0], b.x, b.y);
                MMA_FP16(acc[1][nt], a[1], b.x, b.y);
            }
        }
    };

    // make mbarrier init visible, then kick chunk 0 B + stage chunk 0 A
    __syncthreads();
    if (tid == 0) {
        MBAR_EXPECT_TX(sb_mbar, BBYTES);
        BULK_G2S(sb_b[0], g_WgH, BBYTES, sb_mbar);
    }
#pragma unroll
    for (int s = 0; s < 3; ++s) { ldg_step(0, s); sts_step(As[0], s); }
    __syncthreads();

    int ph0 = 0, ph1 = 0;
    int cur = 0;
    for (int c = 0; c < NCHUNK; ++c) {
        const bool more = (c + 1 < NCHUNK);
        const int nxt = cur ^ 1;
        if (more && tid == 0) {
            MBAR_EXPECT_TX(sb_mbar + nxt * 8, BBYTES);
            BULK_G2S(sb_b[nxt], g_WgH + (c + 1) * BWORDS, BBYTES, sb_mbar + nxt * 8);
        }
        // wait for this chunk's B
        if (cur == 0) { MBAR_WAIT(sb_mbar, ph0); ph0 ^= 1; }
        else          { MBAR_WAIT(sb_mbar + 8, ph1); ph1 ^= 1; }
#pragma unroll
        for (int s = 0; s < 3; ++s) {
            if (more) ldg_step(c + 1, s);
            compute_pair(As[cur], Bs[cur], s * 2);
            if (more) sts_step(As[nxt], s);
        }
        __syncthreads();
        cur = nxt;
    }

    // ---- LN stats reduce + fold constants ----
    smf[SM_PSUM + tid] = psum;
    smf[SM_PSQ + tid] = psq;
    if (tid < NDIM) {
        smf[SM_SFOLD + tid] = g_s[tid];
        smf[SM_BFOLD + tid] = g_bias[tid];
    }
    __syncthreads();
    if (tid < BM) {
        float su = smf[SM_PSUM + 4 * tid] + smf[SM_PSUM + 4 * tid + 1] +
                   smf[SM_PSUM + 4 * tid + 2] + smf[SM_PSUM + 4 * tid + 3];
        float sq = smf[SM_PSQ + 4 * tid] + smf[SM_PSQ + 4 * tid + 1] +
                   smf[SM_PSQ + 4 * tid + 2] + smf[SM_PSQ + 4 * tid + 3];
        float mu = su * (1.f / 768.f);
        float var = sq * (1.f / 768.f) - mu * mu;
        float rs = rsqrtf(var + 1e-5f);
        smf[SM_RSTD + tid] = rs;
        smf[SM_RMU + tid] = rs * mu;
    }
    __syncthreads();

    // ---- epilogue: LN fold + store ----
#pragma unroll
    for (int tmi = 0; tmi < 2; ++tmi) {
        const int rbase = mw * 32 + tmi * 16 + (lane >> 2);
#pragma unroll
        for (int half = 0; half < 2; ++half) {
            const int rr = rbase + half * 8;
            const float rs = smf[SM_RSTD + rr];
            const float rm = smf[SM_RMU + rr];
            float* op = out + (size_t)(bm * BM + rr) * NDIM;
#pragma unroll
            for (int nt = 0; nt < 6; ++nt) {
                const int n0 = nw * 48 + nt * 8 + (lane & 3) * 2;
                float2 v;
                v.x = fmaf(rs, acc[tmi][nt][half * 2 + 0], smf[SM_BFOLD + n0] - rm * smf[SM_SFOLD + n0]);
                v.y = fmaf(rs, acc[tmi][nt][half * 2 + 1], smf[SM_BFOLD + n0 + 1] - rm * smf[SM_SFOLD + n0 + 1]);
                *(float2*)(op + n0) = v;
            }
        }
    }
}

extern "C" void kernel_launch(void* const* d_in, const int* in_sizes, int n_in,
                              void* d_out, int out_size) {
    const float* x    = (const float*)d_in[0];   // [2,64,64,64,96]
    const float* ln_w = (const float*)d_in[1];   // [768]
    const float* ln_b = (const float*)d_in[2];   // [768]
    const float* W    = (const float*)d_in[3];   // [192,768]
    float* out = (float*)d_out;                  // [65536,192]
    (void)in_sizes; (void)n_in; (void)out_size;

    cudaFuncSetAttribute(pm_main, cudaFuncAttributeMaxDynamicSharedMemorySize,
                         SM_WORDS * 4);

    pm_prep<<<FRAG_BLOCKS + COL_BLOCKS, 256>>>(ln_w, ln_b, W);
    pm_main<<<M_TOTAL / BM, TB, SM_WORDS * 4>>>(x, out);
}

// round 14
// speedup vs baseline: 1.2418x; 1.0131x over previous
#include <cuda_runtime.h>
#include <cuda_fp16.h>
#include <cstdint>

// PatchMerging fused as fp16 mma.sync GEMM (fp32 accumulate):
//   out[m,o] = rstd_m * dot(y_m, Wg[o,:]) + (bias_o - rstd_m*mu_m*s_o)
// R14: TB=384, warptile 32x32 (acc=32 regs) -> 24 warps/SM; B frags paired for
//      LDS.128; bulk-B; max LDG->use distance. Attacks measured latency bound.

#define M_TOTAL 65536
#define KDIM    768
#define NDIM    192
#define CH      96
#define BM      64
#define TB      384
#define NCHUNK  8        // K chunks of 96 floats (one patch segment each)
#define APITCH  52       // A row pitch in uint32 (48 data + 4 pad; ldmatrix conflict-free)
#define BWORDS  9216     // B words per chunk
#define BBYTES  (BWORDS * 4)

// ---- device scratch ----
// B fp16, nt-PAIRED fragment order, per chunk 9216 uint32:
//   idx = chunk*9216 + (ntp*6 + ks)*128 + lane*4 + j,  ntp 0..11, ks 0..5, j 0..3
//   nt = ntp*2 + (j>>1), reg = j&1
//   k0 = chunk*96 + ks*16 + reg*8 + (lane&3)*2, n = nt*8 + (lane>>2)
__device__ uint32_t g_WgH[NCHUNK * BWORDS];
__device__ float g_s[NDIM];
__device__ float g_bias[NDIM];

#define MMA_FP16(d, a, b0, b1)                                               \
    asm volatile("mma.sync.aligned.m16n8k16.row.col.f32.f16.f16.f32 "        \
                 "{%0,%1,%2,%3}, {%4,%5,%6,%7}, {%8,%9}, {%0,%1,%2,%3};"     \
                 : "+f"((d)[0]), "+f"((d)[1]), "+f"((d)[2]), "+f"((d)[3])    \
                 : "r"((a)[0]), "r"((a)[1]), "r"((a)[2]), "r"((a)[3]),       \
                   "r"(b0), "r"(b1))

__device__ __forceinline__ uint32_t pack_h2(float a, float b) {
    __half2 h = __floats2half2_rn(a, b);
    return *(uint32_t*)&h;
}

#define MBAR_INIT(a, n) \
    asm volatile("mbarrier.init.shared.b64 [%0], %1;" :: "r"((uint32_t)(a)), "r"((uint32_t)(n)) : "memory")
#define MBAR_EXPECT_TX(a, bytes) \
    asm volatile("mbarrier.arrive.expect_tx.shared.b64 _, [%0], %1;" \
                 :: "r"((uint32_t)(a)), "r"((uint32_t)(bytes)) : "memory")
#define BULK_G2S(dst, src, bytes, mbar) \
    asm volatile("cp.async.bulk.shared::cluster.global.mbarrier::complete_tx::bytes " \
                 "[%0], [%1], %2, [%3];" \
                 :: "r"((uint32_t)(dst)), "l"(src), "r"((uint32_t)(bytes)), \
                    "r"((uint32_t)(mbar)) : "memory")
#define MBAR_WAIT(mb, par) do { \
    uint32_t _mb = (uint32_t)(mb), _pa = (uint32_t)(par), _done; \
    asm volatile("{\n\t.reg .pred p;\n\tmbarrier.try_wait.parity.acquire.cta.shared::cta.b64 p, [%1], %2;\n\tselp.b32 %0,1,0,p;\n\t}" \
        : "=r"(_done) : "r"(_mb), "r"(_pa) : "memory"); \
    if (!_done) { \
        asm volatile("{\n\t.reg .pred P1;\n\tWL%=:\n\tmbarrier.try_wait.parity.acquire.cta.shared::cta.b64 P1, [%0], %1, 0x989680;\n\t@P1 bra.uni WD%=;\n\tbra.uni WL%=;\n\tWD%=:\n\t}" \
            :: "r"(_mb), "r"(_pa) : "memory"); \
    } \
} while (0)

// ---- prep: frag blocks + warp-per-output fold blocks ----
#define NFRAG (NCHUNK * BWORDS)
#define FRAG_BLOCKS (NFRAG / 256)          // 288
#define COL_BLOCKS  (NDIM / 8)             // 24
__global__ void pm_prep(const float* __restrict__ ln_w, const float* __restrict__ ln_b,
                        const float* __restrict__ W) {
    int bid = blockIdx.x;
    if (bid < FRAG_BLOCKS) {
        int idx = bid * 256 + threadIdx.x;
        int chunk = idx / BWORDS, rem = idx % BWORDS;
        int ntp = rem / 768, r2 = rem % 768;
        int ks = r2 >> 7, w = r2 & 127;
        int lane = w >> 2, j = w & 3;
        int nt = ntp * 2 + (j >> 1), reg = j & 1;
        int k0 = chunk * 96 + ks * 16 + reg * 8 + (lane & 3) * 2;
        int n = nt * 8 + (lane >> 2);
        g_WgH[idx] = pack_h2(ln_w[k0] * W[n * KDIM + k0],
                             ln_w[k0 + 1] * W[n * KDIM + k0 + 1]);
    } else {
        int wlocal = threadIdx.x >> 5, lane = threadIdx.x & 31;
        int o = (bid - FRAG_BLOCKS) * 8 + wlocal;
        const float* wr = W + o * KDIM;
        float s = 0.f, b = 0.f;
#pragma unroll
        for (int i = 0; i < KDIM / 32; ++i) {
            int c = lane + i * 32;
            float w = wr[c];
            s = fmaf(ln_w[c], w, s);
            b = fmaf(ln_b[c], w, b);
        }
#pragma unroll
        for (int d = 16; d > 0; d >>= 1) {
            s += __shfl_xor_sync(0xffffffffu, s, d);
            b += __shfl_xor_sync(0xffffffffu, b, d);
        }
        if (lane == 0) {
            g_s[o] = s;
            g_bias[o] = b;
        }
    }
}

// ---- smem uint32-index layout ----
#define SA0      0          // 64*52 = 3328 words per buffer
#define SA1      3328
#define SB0      6656       // 9216 words per buffer
#define SB1      15872
#define SM_MBAR  25088      // 4 words (2 x b64), 8B aligned
#define SM_PSUM  25092      // 384
#define SM_PSQ   25476      // 384
#define SM_RSTD  25860      // 64
#define SM_RMU   25924      // 64
#define SM_SFOLD 25988      // 192
#define SM_BFOLD 26180      // 192
#define SM_WORDS 26372      // 105488 bytes -> 2 CTAs/SM = 211KB

__global__ __launch_bounds__(TB, 2) void pm_main(const float* __restrict__ x,
                                                 float* __restrict__ out) {
    extern __shared__ uint32_t sm[];
    uint32_t* As[2] = {sm + SA0, sm + SA1};
    uint32_t* Bs[2] = {sm + SB0, sm + SB1};
    float* smf = (float*)sm;
    const uint32_t sb_mbar = (uint32_t)__cvta_generic_to_shared(sm + SM_MBAR);
    const uint32_t sb_b[2] = {(uint32_t)__cvta_generic_to_shared(sm + SB0),
                              (uint32_t)__cvta_generic_to_shared(sm + SB1)};

    const int tid = threadIdx.x, lane = tid & 31, wid = tid >> 5;
    const int mw = wid / 6, nw = wid % 6;        // 2x6 warp grid: warptile 32(M) x 32(N)
    const int bm = blockIdx.x;

    // A-gather: 6 threads per row, thread owns 16 contiguous floats of the 96-chunk
    const int r = tid / 6, h = tid % 6;
    const int m = bm * BM + r;
    const int ww = m & 31, hh = (m >> 5) & 31, dd = (m >> 10) & 31, bb = m >> 15;
    const float* xbase = x + ((((long)bb * 64 + 2 * dd) * 64 + 2 * hh) * 64 + 2 * ww) * CH + h * 16;

    if (tid == 0) {
        MBAR_INIT(sb_mbar, 1);
        MBAR_INIT(sb_mbar + 8, 1);
    }

    float acc[2][4][4];
#pragma unroll
    for (int i = 0; i < 2; ++i)
#pragma unroll
        for (int j = 0; j < 4; ++j)
#pragma unroll
            for (int u = 0; u < 4; ++u) acc[i][j][u] = 0.f;

    float psum = 0.f, psq = 0.f;
    float4 av[4];

    auto segp = [&](int ch) {
        return xbase + ((ch >> 2) & 1) * 393216 + ((ch >> 1) & 1) * 6144 + (ch & 1) * 96;
    };
    auto ldg_chunk = [&](int ch) {
        const float* p = segp(ch);
        av[0] = *(const float4*)(p);
        av[1] = *(const float4*)(p + 4);
        av[2] = *(const float4*)(p + 8);
        av[3] = *(const float4*)(p + 12);
    };
    auto sts_chunk = [&](uint32_t* Ad) {
        uint32_t pk[8];
#pragma unroll
        for (int v = 0; v < 4; ++v) {
            float4 t4 = av[v];
            psum += t4.x + t4.y + t4.z + t4.w;
            psq = fmaf(t4.x, t4.x, psq); psq = fmaf(t4.y, t4.y, psq);
            psq = fmaf(t4.z, t4.z, psq); psq = fmaf(t4.w, t4.w, psq);
            pk[v * 2]     = pack_h2(t4.x, t4.y);
            pk[v * 2 + 1] = pack_h2(t4.z, t4.w);
        }
        uint32_t* dst = Ad + r * APITCH + h * 8;
        *(uint4*)(dst)     = *(uint4*)(pk);
        *(uint4*)(dst + 4) = *(uint4*)(pk + 4);
    };
    auto compute = [&](const uint32_t* Ad, const uint32_t* Bd) {
#pragma unroll
        for (int ks = 0; ks < 6; ++ks) {
            uint32_t a[2][4];
#pragma unroll
            for (int tmi = 0; tmi < 2; ++tmi) {
                int row = mw * 32 + tmi * 16 + (lane & 15);
                const uint32_t* ap = Ad + row * APITCH + ks * 8 + (lane >> 4) * 4;
                uint32_t sa = (uint32_t)__cvta_generic_to_shared(ap);
                asm volatile("ldmatrix.sync.aligned.m8n8.x4.shared.b16 {%0,%1,%2,%3}, [%4];"
                             : "=r"(a[tmi][0]), "=r"(a[tmi][1]), "=r"(a[tmi][2]), "=r"(a[tmi][3])
                             : "r"(sa));
            }
#pragma unroll
            for (int p = 0; p < 2; ++p) {
                // one LDS.128 serves two adjacent nt
                uint4 b = *(const uint4*)(Bd + ((nw * 2 + p) * 6 + ks) * 128 + lane * 4);
                MMA_FP16(acc[0][p * 2],     a[0], b.x, b.y);
                MMA_FP16(acc[1][p * 2],     a[1], b.x, b.y);
                MMA_FP16(acc[0][p * 2 + 1], a[0], b.z, b.w);
                MMA_FP16(acc[1][p * 2 + 1], a[1], b.z, b.w);
            }
        }
    };

    // make mbarrier init visible, then kick chunk 0 B + stage chunk 0 A
    __syncthreads();
    if (tid == 0) {
        MBAR_EXPECT_TX(sb_mbar, BBYTES);
        BULK_G2S(sb_b[0], g_WgH, BBYTES, sb_mbar);
    }
    ldg_chunk(0);
    sts_chunk(As[0]);
    __syncthreads();

    int ph0 = 0, ph1 = 0;
    int cur = 0;
    for (int c = 0; c < NCHUNK; ++c) {
        const bool more = (c + 1 < NCHUNK);
        const int nxt = cur ^ 1;
        if (more) {
            if (tid == 0) {
                MBAR_EXPECT_TX(sb_mbar + nxt * 8, BBYTES);
                BULK_G2S(sb_b[nxt], g_WgH + (c + 1) * BWORDS, BBYTES, sb_mbar + nxt * 8);
            }
            ldg_chunk(c + 1);   // DRAM latency overlaps mbar wait + full compute
        }
        if (cur == 0) { MBAR_WAIT(sb_mbar, ph0); ph0 ^= 1; }
        else          { MBAR_WAIT(sb_mbar + 8, ph1); ph1 ^= 1; }
        compute(As[cur], Bs[cur]);
        if (more) sts_chunk(As[nxt]);
        __syncthreads();
        cur = nxt;
    }

    // ---- LN stats reduce + fold constants ----
    smf[SM_PSUM + tid] = psum;
    smf[SM_PSQ + tid] = psq;
    if (tid < NDIM) {
        smf[SM_SFOLD + tid] = g_s[tid];
        smf[SM_BFOLD + tid] = g_bias[tid];
    }
    __syncthreads();
    if (tid < BM) {
        float su = 0.f, sq = 0.f;
#pragma unroll
        for (int i = 0; i < 6; ++i) {
            su += smf[SM_PSUM + 6 * tid + i];
            sq += smf[SM_PSQ + 6 * tid + i];
        }
        float mu = su * (1.f / 768.f);
        float var = sq * (1.f / 768.f) - mu * mu;
        float rs = rsqrtf(var + 1e-5f);
        smf[SM_RSTD + tid] = rs;
        smf[SM_RMU + tid] = rs * mu;
    }
    __syncthreads();

    // ---- epilogue: LN fold + store ----
#pragma unroll
    for (int tmi = 0; tmi < 2; ++tmi) {
        const int rbase = mw * 32 + tmi * 16 + (lane >> 2);
#pragma unroll
        for (int half = 0; half < 2; ++half) {
            const int rr = rbase + half * 8;
            const float rs = smf[SM_RSTD + rr];
            const float rm = smf[SM_RMU + rr];
            float* op = out + (size_t)(bm * BM + rr) * NDIM;
#pragma unroll
            for (int nt = 0; nt < 4; ++nt) {
                const int n0 = nw * 32 + nt * 8 + (lane & 3) * 2;
                float2 v;
                v.x = fmaf(rs, acc[tmi][nt][half * 2 + 0], smf[SM_BFOLD + n0] - rm * smf[SM_SFOLD + n0]);
                v.y = fmaf(rs, acc[tmi][nt][half * 2 + 1], smf[SM_BFOLD + n0 + 1] - rm * smf[SM_SFOLD + n0 + 1]);
                *(float2*)(op + n0) = v;
            }
        }
    }
}

extern "C" void kernel_launch(void* const* d_in, const int* in_sizes, int n_in,
                              void* d_out, int out_size) {
    const float* x    = (const float*)d_in[0];   // [2,64,64,64,96]
    const float* ln_w = (const float*)d_in[1];   // [768]
    const float* ln_b = (const float*)d_in[2];   // [768]
    const float* W    = (const float*)d_in[3];   // [192,768]
    float* out = (float*)d_out;                  // [65536,192]
    (void)in_sizes; (void)n_in; (void)out_size;

    cudaFuncSetAttribute(pm_main, cudaFuncAttributeMaxDynamicSharedMemorySize,
                         SM_WORDS * 4);

    pm_prep<<<FRAG_BLOCKS + COL_BLOCKS, 256>>>(ln_w, ln_b, W);
    pm_main<<<M_TOTAL / BM, TB, SM_WORDS * 4>>>(x, out);
}

// round 16
// speedup vs baseline: 1.4376x; 1.1576x over previous
#include <cuda_runtime.h>
#include <cuda_fp16.h>
#include <cstdint>

// PatchMerging fused as fp16 mma.sync GEMM (fp32 accumulate):
//   out[m,o] = rstd_m * dot(y_m, Wg[o,:]) + (bias_o - rstd_m*mu_m*s_o)
// R15: R8 shape (TB=256, warptile 32x48, 2 CTAs/SM) + bulk-B + paired-B LDS.128
//      + COALESCED interleaved A-gather (the census said A-LDG was the top L1 item).

#define M_TOTAL 65536
#define KDIM    768
#define NDIM    192
#define CH      96
#define BM      64
#define TB      256
#define NCHUNK  8        // K chunks of 96 floats (one patch segment each)
#define APITCH  52       // A row pitch in uint32 (48 data + 4 pad; ldmatrix conflict-free)
#define BWORDS  9216     // B words per chunk
#define BBYTES  (BWORDS * 4)

// ---- device scratch ----
// B fp16, nt-PAIRED fragment order, per chunk 9216 uint32:
//   idx = chunk*9216 + (ntp*6 + ks)*128 + lane*4 + j,  ntp 0..11, ks 0..5, j 0..3
//   nt = ntp*2 + (j>>1), reg = j&1
//   k0 = chunk*96 + ks*16 + reg*8 + (lane&3)*2, n = nt*8 + (lane>>2)
__device__ uint32_t g_WgH[NCHUNK * BWORDS];
__device__ float g_s[NDIM];
__device__ float g_bias[NDIM];

#define MMA_FP16(d, a, b0, b1)                                               \
    asm volatile("mma.sync.aligned.m16n8k16.row.col.f32.f16.f16.f32 "        \
                 "{%0,%1,%2,%3}, {%4,%5,%6,%7}, {%8,%9}, {%0,%1,%2,%3};"     \
                 : "+f"((d)[0]), "+f"((d)[1]), "+f"((d)[2]), "+f"((d)[3])    \
                 : "r"((a)[0]), "r"((a)[1]), "r"((a)[2]), "r"((a)[3]),       \
                   "r"(b0), "r"(b1))

__device__ __forceinline__ uint32_t pack_h2(float a, float b) {
    __half2 h = __floats2half2_rn(a, b);
    return *(uint32_t*)&h;
}

#define MBAR_INIT(a, n) \
    asm volatile("mbarrier.init.shared.b64 [%0], %1;" :: "r"((uint32_t)(a)), "r"((uint32_t)(n)) : "memory")
#define MBAR_EXPECT_TX(a, bytes) \
    asm volatile("mbarrier.arrive.expect_tx.shared.b64 _, [%0], %1;" \
                 :: "r"((uint32_t)(a)), "r"((uint32_t)(bytes)) : "memory")
#define BULK_G2S(dst, src, bytes, mbar) \
    asm volatile("cp.async.bulk.shared::cluster.global.mbarrier::complete_tx::bytes " \
                 "[%0], [%1], %2, [%3];" \
                 :: "r"((uint32_t)(dst)), "l"(src), "r"((uint32_t)(bytes)), \
                    "r"((uint32_t)(mbar)) : "memory")
#define MBAR_WAIT(mb, par) do { \
    uint32_t _mb = (uint32_t)(mb), _pa = (uint32_t)(par), _done; \
    asm volatile("{\n\t.reg .pred p;\n\tmbarrier.try_wait.parity.acquire.cta.shared::cta.b64 p, [%1], %2;\n\tselp.b32 %0,1,0,p;\n\t}" \
        : "=r"(_done) : "r"(_mb), "r"(_pa) : "memory"); \
    if (!_done) { \
        asm volatile("{\n\t.reg .pred P1;\n\tWL%=:\n\tmbarrier.try_wait.parity.acquire.cta.shared::cta.b64 P1, [%0], %1, 0x989680;\n\t@P1 bra.uni WD%=;\n\tbra.uni WL%=;\n\tWD%=:\n\t}" \
            :: "r"(_mb), "r"(_pa) : "memory"); \
    } \
} while (0)

// ---- prep: frag blocks + warp-per-output fold blocks ----
#define NFRAG (NCHUNK * BWORDS)
#define FRAG_BLOCKS (NFRAG / 256)          // 288
#define COL_BLOCKS  (NDIM / 8)             // 24
__global__ void pm_prep(const float* __restrict__ ln_w, const float* __restrict__ ln_b,
                        const float* __restrict__ W) {
    int bid = blockIdx.x;
    if (bid < FRAG_BLOCKS) {
        int idx = bid * 256 + threadIdx.x;
        int chunk = idx / BWORDS, rem = idx % BWORDS;
        int ntp = rem / 768, r2 = rem % 768;
        int ks = r2 >> 7, w = r2 & 127;
        int lane = w >> 2, j = w & 3;
        int nt = ntp * 2 + (j >> 1), reg = j & 1;
        int k0 = chunk * 96 + ks * 16 + reg * 8 + (lane & 3) * 2;
        int n = nt * 8 + (lane >> 2);
        g_WgH[idx] = pack_h2(ln_w[k0] * W[n * KDIM + k0],
                             ln_w[k0 + 1] * W[n * KDIM + k0 + 1]);
    } else {
        int wlocal = threadIdx.x >> 5, lane = threadIdx.x & 31;
        int o = (bid - FRAG_BLOCKS) * 8 + wlocal;
        const float* wr = W + o * KDIM;
        float s = 0.f, b = 0.f;
#pragma unroll
        for (int i = 0; i < KDIM / 32; ++i) {
            int c = lane + i * 32;
            float w = wr[c];
            s = fmaf(ln_w[c], w, s);
            b = fmaf(ln_b[c], w, b);
        }
#pragma unroll
        for (int d = 16; d > 0; d >>= 1) {
            s += __shfl_xor_sync(0xffffffffu, s, d);
            b += __shfl_xor_sync(0xffffffffu, b, d);
        }
        if (lane == 0) {
            g_s[o] = s;
            g_bias[o] = b;
        }
    }
}

// ---- smem uint32-index layout ----
#define SA0      0          // 64*52 = 3328 words per buffer
#define SA1      3328
#define SB0      6656       // 9216 words per buffer
#define SB1      15872
#define SM_MBAR  25088      // 4 words (2 x b64), 8B aligned
#define SM_PSUM  25092      // 256
#define SM_PSQ   25348      // 256
#define SM_RSTD  25604      // 64
#define SM_RMU   25668      // 64
#define SM_SFOLD 25732      // 192
#define SM_BFOLD 25924      // 192
#define SM_WORDS 26116      // 104464 bytes -> 2 CTAs/SM

__global__ __launch_bounds__(TB, 2) void pm_main(const float* __restrict__ x,
                                                 float* __restrict__ out) {
    extern __shared__ uint32_t sm[];
    uint32_t* As[2] = {sm + SA0, sm + SA1};
    uint32_t* Bs[2] = {sm + SB0, sm + SB1};
    float* smf = (float*)sm;
    const uint32_t sb_mbar = (uint32_t)__cvta_generic_to_shared(sm + SM_MBAR);
    const uint32_t sb_b[2] = {(uint32_t)__cvta_generic_to_shared(sm + SB0),
                              (uint32_t)__cvta_generic_to_shared(sm + SB1)};

    const int tid = threadIdx.x, lane = tid & 31, wid = tid >> 5;
    const int mw = wid >> 2, nw = wid & 3;       // 2x4 warp grid: warptile 32(M) x 48(N)
    const int bm = blockIdx.x;

    // A-gather: 4 threads per row, INTERLEAVED float4 ownership:
    // thread h owns float4 #(h + s*4) of the 24 float4s in a 96-float chunk (s=0..5).
    // -> per LDG.128, 4 lanes cover one contiguous 64B run per row (coalesced).
    const int r = tid >> 2, h = tid & 3;
    const int m = bm * BM + r;
    const int ww = m & 31, hh = (m >> 5) & 31, dd = (m >> 10) & 31, bb = m >> 15;
    const float* xbase = x + ((((long)bb * 64 + 2 * dd) * 64 + 2 * hh) * 64 + 2 * ww) * CH;

    if (tid == 0) {
        MBAR_INIT(sb_mbar, 1);
        MBAR_INIT(sb_mbar + 8, 1);
    }

    float acc[2][6][4];
#pragma unroll
    for (int i = 0; i < 2; ++i)
#pragma unroll
        for (int j = 0; j < 6; ++j)
#pragma unroll
            for (int u = 0; u < 4; ++u) acc[i][j][u] = 0.f;

    float psum = 0.f, psq = 0.f;
    float4 av[3];

    auto segp = [&](int ch) {
        return xbase + ((ch >> 2) & 1) * 393216 + ((ch >> 1) & 1) * 6144 + (ch & 1) * 96;
    };
    // half-chunk gather: steps s = half*3 .. half*3+2, float4 index h + s*4
    auto ldg_half = [&](int ch, int half) {
        const float* p = segp(ch);
#pragma unroll
        for (int v = 0; v < 3; ++v) {
            int s = half * 3 + v;
            av[v] = *(const float4*)(p + (h + s * 4) * 4);
        }
    };
    auto sts_half = [&](uint32_t* Ad, int half) {
#pragma unroll
        for (int v = 0; v < 3; ++v) {
            int s = half * 3 + v;
            float4 t4 = av[v];
            psum += t4.x + t4.y + t4.z + t4.w;
            psq = fmaf(t4.x, t4.x, psq); psq = fmaf(t4.y, t4.y, psq);
            psq = fmaf(t4.z, t4.z, psq); psq = fmaf(t4.w, t4.w, psq);
            uint2 pk;
            pk.x = pack_h2(t4.x, t4.y);
            pk.y = pack_h2(t4.z, t4.w);
            *(uint2*)(Ad + r * APITCH + (h + s * 4) * 2) = pk;   // STS.64, 8B aligned
        }
    };
    auto compute_half = [&](const uint32_t* Ad, const uint32_t* Bd, int ks0) {
#pragma unroll
        for (int kk = 0; kk < 3; ++kk) {
            const int ks = ks0 + kk;
            uint32_t a[2][4];
#pragma unroll
            for (int tmi = 0; tmi < 2; ++tmi) {
                int row = mw * 32 + tmi * 16 + (lane & 15);
                const uint32_t* ap = Ad + row * APITCH + ks * 8 + (lane >> 4) * 4;
                uint32_t sa = (uint32_t)__cvta_generic_to_shared(ap);
                asm volatile("ldmatrix.sync.aligned.m8n8.x4.shared.b16 {%0,%1,%2,%3}, [%4];"
                             : "=r"(a[tmi][0]), "=r"(a[tmi][1]), "=r"(a[tmi][2]), "=r"(a[tmi][3])
                             : "r"(sa));
            }
#pragma unroll
            for (int p = 0; p < 3; ++p) {
                // one LDS.128 serves two adjacent nt
                uint4 b = *(const uint4*)(Bd + ((nw * 3 + p) * 6 + ks) * 128 + lane * 4);
                MMA_FP16(acc[0][p * 2],     a[0], b.x, b.y);
                MMA_FP16(acc[1][p * 2],     a[1], b.x, b.y);
                MMA_FP16(acc[0][p * 2 + 1], a[0], b.z, b.w);
                MMA_FP16(acc[1][p * 2 + 1], a[1], b.z, b.w);
            }
        }
    };

    // make mbarrier init visible, then kick chunk 0 B + stage chunk 0 A
    __syncthreads();
    if (tid == 0) {
        MBAR_EXPECT_TX(sb_mbar, BBYTES);
        BULK_G2S(sb_b[0], g_WgH, BBYTES, sb_mbar);
    }
    ldg_half(0, 0); sts_half(As[0], 0);
    ldg_half(0, 1); sts_half(As[0], 1);
    __syncthreads();

    int ph0 = 0, ph1 = 0;
    int cur = 0;
    for (int c = 0; c < NCHUNK; ++c) {
        const bool more = (c + 1 < NCHUNK);
        const int nxt = cur ^ 1;
        if (more) {
            if (tid == 0) {
                MBAR_EXPECT_TX(sb_mbar + nxt * 8, BBYTES);
                BULK_G2S(sb_b[nxt], g_WgH + (c + 1) * BWORDS, BBYTES, sb_mbar + nxt * 8);
            }
            ldg_half(c + 1, 0);            // DRAM latency covered by wait + compute
        }
        if (cur == 0) { MBAR_WAIT(sb_mbar, ph0); ph0 ^= 1; }
        else          { MBAR_WAIT(sb_mbar + 8, ph1); ph1 ^= 1; }
        compute_half(As[cur], Bs[cur], 0);
        if (more) {
            sts_half(As[nxt], 0);
            ldg_half(c + 1, 1);
        }
        compute_half(As[cur], Bs[cur], 3);
        if (more) sts_half(As[nxt], 1);
        __syncthreads();
        cur = nxt;
    }

    // ---- LN stats reduce + fold constants ----
    smf[SM_PSUM + tid] = psum;
    smf[SM_PSQ + tid] = psq;
    if (tid < NDIM) {
        smf[SM_SFOLD + tid] = g_s[tid];
        smf[SM_BFOLD + tid] = g_bias[tid];
    }
    __syncthreads();
    if (tid < BM) {
        float su = smf[SM_PSUM + 4 * tid] + smf[SM_PSUM + 4 * tid + 1] +
                   smf[SM_PSUM + 4 * tid + 2] + smf[SM_PSUM + 4 * tid + 3];
        float sq = smf[SM_PSQ + 4 * tid] + smf[SM_PSQ + 4 * tid + 1] +
                   smf[SM_PSQ + 4 * tid + 2] + smf[SM_PSQ + 4 * tid + 3];
        float mu = su * (1.f / 768.f);
        float var = sq * (1.f / 768.f) - mu * mu;
        float rs = rsqrtf(var + 1e-5f);
        smf[SM_RSTD + tid] = rs;
        smf[SM_RMU + tid] = rs * mu;
    }
    __syncthreads();

    // ---- epilogue: LN fold + store ----
#pragma unroll
    for (int tmi = 0; tmi < 2; ++tmi) {
        const int rbase = mw * 32 + tmi * 16 + (lane >> 2);
#pragma unroll
        for (int half = 0; half < 2; ++half) {
            const int rr = rbase + half * 8;
            const float rs = smf[SM_RSTD + rr];
            const float rm = smf[SM_RMU + rr];
            float* op = out + (size_t)(bm * BM + rr) * NDIM;
#pragma unroll
            for (int nt = 0; nt < 6; ++nt) {
                const int n0 = nw * 48 + nt * 8 + (lane & 3) * 2;
                float2 v;
                v.x = fmaf(rs, acc[tmi][nt][half * 2 + 0], smf[SM_BFOLD + n0] - rm * smf[SM_SFOLD + n0]);
                v.y = fmaf(rs, acc[tmi][nt][half * 2 + 1], smf[SM_BFOLD + n0 + 1] - rm * smf[SM_SFOLD + n0 + 1]);
                *(float2*)(op + n0) = v;
            }
        }
    }
}

extern "C" void kernel_launch(void* const* d_in, const int* in_sizes, int n_in,
                              void* d_out, int out_size) {
    const float* x    = (const float*)d_in[0];   // [2,64,64,64,96]
    const float* ln_w = (const float*)d_in[1];   // [768]
    const float* ln_b = (const float*)d_in[2];   // [768]
    const float* W    = (const float*)d_in[3];   // [192,768]
    float* out = (float*)d_out;                  // [65536,192]
    (void)in_sizes; (void)n_in; (void)out_size;

    cudaFuncSetAttribute(pm_main, cudaFuncAttributeMaxDynamicSharedMemorySize,
                         SM_WORDS * 4);

    pm_prep<<<FRAG_BLOCKS + COL_BLOCKS, 256>>>(ln_w, ln_b, W);
    pm_main<<<M_TOTAL / BM, TB, SM_WORDS * 4>>>(x, out);
}